// round 15
// baseline (speedup 1.0000x reference)
#include <cuda_runtime.h>
#include <cstdint>

#define TT 16384
#define EE 512
#define NB 64
#define SPLITS 6

#define SZ_PQ (192*512)
#define SZ_CK (256*512)
#define OFF_PQ 0
#define OFF_CK (SZ_PQ)
#define OFF_CV (SZ_PQ + SZ_CK)
#define SLICE_SZ (SZ_PQ + 2*SZ_CK)   // 360448

__device__ float g_part[SPLITS * SLICE_SZ];
__device__ float g_acc[SLICE_SZ];
__device__ float g_A3[192*512];

typedef unsigned long long u64;
typedef unsigned int u32;

// ===================== packed fp32 helpers ===================
__device__ __forceinline__ u64 pack2(float lo, float hi){
  u64 r; asm("mov.b64 %0, {%1,%2};" : "=l"(r) : "f"(lo), "f"(hi)); return r;
}
__device__ __forceinline__ float2 unpack2(u64 v){
  float2 r; asm("mov.b64 {%0,%1}, %2;" : "=f"(r.x), "=f"(r.y) : "l"(v)); return r;
}
__device__ __forceinline__ void fma2(u64 &d, u64 a, u64 b){
  asm("fma.rn.f32x2 %0, %1, %2, %0;" : "+l"(d) : "l"(a), "l"(b));
}
__device__ __forceinline__ void add2(u64 &d, u64 a){
  asm("add.rn.f32x2 %0, %0, %1;" : "+l"(d) : "l"(a));
}
__device__ __forceinline__ void mul2(u64 &d, u64 a){
  asm("mul.rn.f32x2 %0, %0, %1;" : "+l"(d) : "l"(a));
}

// ===================== mma.sync building blocks ============================
__device__ __forceinline__ u32 smem_u32(const void* p){
  u32 a; asm("{ .reg .u64 t; cvta.to.shared.u64 t, %1; cvt.u32.u64 %0, t; }" : "=r"(a) : "l"(p));
  return a;
}
__device__ __forceinline__ void ldsm4(u32 addr, u32* r){
  asm volatile("ldmatrix.sync.aligned.m8n8.x4.shared.b16 {%0,%1,%2,%3}, [%4];"
    : "=r"(r[0]),"=r"(r[1]),"=r"(r[2]),"=r"(r[3]) : "r"(addr));
}
__device__ __forceinline__ void mma16816(float* c, const u32* a, u32 b0, u32 b1){
  asm volatile("mma.sync.aligned.m16n8k16.row.col.f32.bf16.bf16.f32 "
    "{%0,%1,%2,%3}, {%4,%5,%6,%7}, {%8,%9}, {%0,%1,%2,%3};"
    : "+f"(c[0]),"+f"(c[1]),"+f"(c[2]),"+f"(c[3])
    : "r"(a[0]),"r"(a[1]),"r"(a[2]),"r"(a[3]), "r"(b0),"r"(b1));
}

// fp32x4 -> bf16 hi/lo pairs
__device__ __forceinline__ void cvt_hilo(float4 v, uint2& hi, uint2& lo){
  u32 h01,h23,l01,l23;
  asm("cvt.rn.bf16x2.f32 %0, %1, %2;" : "=r"(h01) : "f"(v.y), "f"(v.x));
  asm("cvt.rn.bf16x2.f32 %0, %1, %2;" : "=r"(h23) : "f"(v.w), "f"(v.z));
  float hx=__uint_as_float(h01<<16), hy=__uint_as_float(h01&0xFFFF0000u);
  float hz=__uint_as_float(h23<<16), hw=__uint_as_float(h23&0xFFFF0000u);
  asm("cvt.rn.bf16x2.f32 %0, %1, %2;" : "=r"(l01) : "f"(v.y-hy), "f"(v.x-hx));
  asm("cvt.rn.bf16x2.f32 %0, %1, %2;" : "=r"(l23) : "f"(v.w-hw), "f"(v.z-hz));
  hi = make_uint2(h01,h23); lo = make_uint2(l01,l23);
}

// Tile geometry: CTA 128(M) x 64(N) x 32(K) chunks; bf16 rows of 64B,
// XOR swizzle on bits [4:6].
#define A_TILE_B 8192      // 128 rows x 64B
#define B_TILE_B 4096      // 64 rows x 64B
#define BUF_BYTES (2*A_TILE_B + 2*B_TILE_B)   // 24576: Ahi|Alo|Bhi|Blo
#define DYN_SMEM  (2*BUF_BYTES + 1024)

// attn smem: Ks[16][520] + Vs[16][520] fp32
#define ATTN_ROW   520
#define ATTN_SMEM  (2*16*ATTN_ROW*4)

__device__ __forceinline__ u32 cka(u32 row, u32 kc8){
  return (row*64u + kc8*16u) ^ ((row & 7u) << 4);
}
__device__ __forceinline__ u32 swa(u32 row, u32 k){
  return ((row*64u + ((k>>3)<<4)) ^ ((row & 7u) << 4)) + (k & 4u)*2u;
}

// per-warp compute of one kc=32 chunk; warp tile 32x32, 3-term bf16
__device__ __forceinline__ void chunk_compute(
    u32 sAhi, u32 sAlo, u32 sBhi, u32 sBlo,
    int wm, int wn, int lane, float acc[2][4][4])
{
  u32 lrow = lane & 15, lkh = (u32)lane >> 4;
  #pragma unroll
  for (int s=0; s<2; s++){
    u32 kc8 = 2u*s + lkh;
    u32 bh[2][4], bl[2][4];
    #pragma unroll
    for (int nt2=0; nt2<2; nt2++){
      u32 off = cka((u32)(wn*32 + nt2*16) + lrow, kc8);
      ldsm4(sBhi + off, bh[nt2]);
      ldsm4(sBlo + off, bl[nt2]);
    }
    #pragma unroll
    for (int mt=0; mt<2; mt++){
      u32 ah[4], al[4];
      u32 off = cka((u32)(wm*32 + mt*16) + lrow, kc8);
      ldsm4(sAhi + off, ah);
      ldsm4(sAlo + off, al);
      #pragma unroll
      for (int n8=0; n8<4; n8++){
        int g = n8 >> 1, o = n8 & 1;
        u32 b0h = bh[g][o], b1h = bh[g][o+2];
        u32 b0l = bl[g][o], b1l = bl[g][o+2];
        mma16816(acc[mt][n8], ah, b0h, b1h);
        mma16816(acc[mt][n8], ah, b0l, b1l);
        mma16816(acc[mt][n8], al, b0h, b1h);
      }
    }
  }
}

struct LoadCtx {
  const float* aptr;
  const float* bptr;
  u32 soA[4];
  u32 soB[2];
};

__device__ __forceinline__ void fill_buf(const LoadCtx& L, char* base, int kb){
  #pragma unroll
  for (int i=0;i<4;i++){
    float4 v = *(const float4*)(L.aptr + kb + i*4);
    uint2 hi, lo;
    cvt_hilo(v, hi, lo);
    *(uint2*)(base + L.soA[i]) = hi;
    *(uint2*)(base + A_TILE_B + L.soA[i]) = lo;
  }
  #pragma unroll
  for (int i=0;i<2;i++){
    float4 v = *(const float4*)(L.bptr + kb + i*4);
    uint2 hi, lo;
    cvt_hilo(v, hi, lo);
    *(uint2*)(base + 2*A_TILE_B + L.soB[i]) = hi;
    *(uint2*)(base + 2*A_TILE_B + B_TILE_B + L.soB[i]) = lo;
  }
}

__device__ __forceinline__ void fill_buf_pref(
    const LoadCtx& L, char* base, const float4* ga, const float4* gb){
  #pragma unroll
  for (int i=0;i<4;i++){
    uint2 hi, lo;
    cvt_hilo(ga[i], hi, lo);
    *(uint2*)(base + L.soA[i]) = hi;
    *(uint2*)(base + A_TILE_B + L.soA[i]) = lo;
  }
  #pragma unroll
  for (int i=0;i<2;i++){
    uint2 hi, lo;
    cvt_hilo(gb[i], hi, lo);
    *(uint2*)(base + 2*A_TILE_B + L.soB[i]) = hi;
    *(uint2*)(base + 2*A_TILE_B + B_TILE_B + L.soB[i]) = lo;
  }
}

// 32-k chunks, double-buffered, single-chunk register prefetch
__device__ __forceinline__ void gemm_mainloop(
    const LoadCtx& L, char* sbp, u32 sb, int cs, int nch,
    int wm, int wn, int lane, float acc[2][4][4])
{
  fill_buf(L, sbp, cs*32);
  __syncthreads();

  for (int c = 0; c < nch; c++){
    int buf = c & 1;
    float4 ga[4], gb[2];
    if (c + 1 < nch){
      int kb = (cs + c + 1)*32;
      #pragma unroll
      for (int i=0;i<4;i++) ga[i] = *(const float4*)(L.aptr + kb + i*4);
      #pragma unroll
      for (int i=0;i<2;i++) gb[i] = *(const float4*)(L.bptr + kb + i*4);
    }
    u32 bufb = sb + (u32)buf*BUF_BYTES;
    chunk_compute(bufb, bufb+A_TILE_B, bufb+2*A_TILE_B, bufb+2*A_TILE_B+B_TILE_B,
                  wm, wn, lane, acc);
    if (c + 1 < nch){
      fill_buf_pref(L, sbp + (buf^1)*BUF_BYTES, ga, gb);
    }
    __syncthreads();
  }
}

// ===========================================================================
// Stage A: partial GEMMs (PQ/CK/CV) with split-K.  grid (nt=8, mtg=6, s=6)
// ===========================================================================
__global__ __launch_bounds__(256, 2) void gemm_a_mma(
    const float* __restrict__ x, const float* __restrict__ Wq,
    const float* __restrict__ Wk, const float* __restrict__ Wv)
{
  extern __shared__ char dynsmem[];
  u32 raw = smem_u32(dynsmem);
  u32 sb = (raw + 1023u) & ~1023u;
  char* sbp = dynsmem + (sb - raw);

  int nt  = blockIdx.x;
  int mtg = blockIdx.y;
  int s   = blockIdx.z;
  int t   = threadIdx.x;

  int mat   = (mtg < 2) ? 0 : (mtg < 4) ? 1 : 2;
  int mbase = (mtg & 1) ? ((mat == 0) ? 64 : 128) : 0;
  const float* __restrict__ W = (mat==0) ? Wq : (mat==1) ? Wk : Wv;
  int obase = (mat==0) ? OFF_PQ : (mat==1) ? OFF_CK : OFF_CV;

  // 512 chunks of 32 over 6 splits (2 x 86 + 4 x 85 = 512)
  int cs  = s*85 + min(s, 2);
  int nch = 85 + (s < 2 ? 1 : 0);

  int arow  = t >> 1;
  int khalf = (t & 1) * 16;
  int brow  = t >> 2;
  int bk8   = (t & 3) * 8;

  int m = mbase + arow;
  int b, ch;
  if (mat == 0){ b = m/3; ch = m - b*3; }
  else         { b = m/4; ch = 3 + (m - b*4); }

  LoadCtx L;
  L.aptr = x + ((size_t)(b*7 + ch))*TT + khalf;
  L.bptr = W + ((size_t)(nt*64 + brow))*TT + bk8;
  #pragma unroll
  for (int i=0;i<4;i++) L.soA[i] = swa((u32)arow, (u32)(khalf + i*4));
  #pragma unroll
  for (int i=0;i<2;i++) L.soB[i] = swa((u32)brow, (u32)(bk8 + i*4));

  int w = t >> 5, lane = t & 31;
  int wm = w >> 1, wn = w & 1;

  float acc[2][4][4];
  #pragma unroll
  for (int i=0;i<2;i++)
    #pragma unroll
    for (int j=0;j<4;j++)
      #pragma unroll
      for (int q=0;q<4;q++) acc[i][j][q] = 0.f;

  gemm_mainloop(L, sbp, sb, cs, nch, wm, wn, lane, acc);

  float* dst = g_part + (size_t)s*SLICE_SZ + obase;
  int rl = lane >> 2, cl = 2*(lane & 3);
  #pragma unroll
  for (int mt=0; mt<2; mt++){
    int r0 = mbase + wm*32 + mt*16 + rl;
    #pragma unroll
    for (int n8=0; n8<4; n8++){
      int col = nt*64 + wn*32 + n8*8 + cl;
      *(float2*)&dst[(size_t)r0*EE + col]     = make_float2(acc[mt][n8][0], acc[mt][n8][1]);
      *(float2*)&dst[(size_t)(r0+8)*EE + col] = make_float2(acc[mt][n8][2], acc[mt][n8][3]);
    }
  }
}

// ===========================================================================
// Split-K reduction (deterministic)
// ===========================================================================
__global__ __launch_bounds__(256) void reduce_kernel()
{
  int i = blockIdx.x*256 + threadIdx.x;
  if (i >= SLICE_SZ) return;
  float s = 0.f;
  #pragma unroll
  for (int sl=0; sl<SPLITS; sl++) s += g_part[(size_t)sl*SLICE_SZ + i];
  g_acc[i] = s;
}

// ===========================================================================
// Attention: K/V built once per block (2x redundancy instead of 4x).
// grid (2 e-chunks, NB batches), 256 threads; dynamic smem 65 KB.
// Each thread builds 2 f-columns, then runs online softmax for 1 e-column.
// ===========================================================================
__global__ __launch_bounds__(256) void attn_kernel(
  const float* __restrict__ W1, const float* __restrict__ W2,
  const float* __restrict__ bq, const float* __restrict__ bk,
  const float* __restrict__ bv, const float* __restrict__ W3)
{
  extern __shared__ float sKV[];
  float* Ks = sKV;
  float* Vs = sKV + 16*ATTN_ROW;

  int b = blockIdx.y;
  int t = threadIdx.x;
  int e = blockIdx.x*256 + t;

  const float* __restrict__ PQb = g_acc + OFF_PQ + (size_t)b*3*EE;
  const float* __restrict__ CKb = g_acc + OFF_CK + (size_t)b*4*EE;
  const float* __restrict__ CVb = g_acc + OFF_CV + (size_t)b*4*EE;

  // ---- build K,V once: thread handles f = t, t+256 ----
  #pragma unroll
  for (int r=0; r<2; r++){
    int f = r*256 + t;
    float k0 = CKb[f], k1 = CKb[EE+f], k2 = CKb[2*EE+f], k3 = CKb[3*EE+f];
    float v0 = CVb[f], v1 = CVb[EE+f], v2 = CVb[2*EE+f], v3 = CVb[3*EE+f];
    float bkf = bk[f], bvf = bv[f];
    #pragma unroll
    for (int c=0;c<16;c++){
      const float* w2 = W2 + c*4;
      Ks[c*ATTN_ROW + f] = w2[0]*k0 + w2[1]*k1 + w2[2]*k2 + w2[3]*k3 + bkf;
      Vs[c*ATTN_ROW + f] = w2[0]*v0 + w2[1]*v1 + w2[2]*v2 + w2[3]*v3 + bvf;
    }
  }

  // ---- q (scale folded) ----
  float p0 = PQb[e], p1 = PQb[EE+e], p2 = PQb[2*EE+e];
  float bqe = bq[e];
  u64 q2[16];
  #pragma unroll
  for (int c=0;c<16;c++){
    float qc = 0.25f*(W1[c*3]*p0 + W1[c*3+1]*p1 + W1[c*3+2]*p2 + bqe);
    q2[c] = pack2(qc, qc);
  }
  __syncthreads();

  // ---- online softmax over f = 0..511 ----
  float mmax = -1e30f;
  u64 Z2 = 0ULL;
  u64 acc2[16];
  #pragma unroll
  for (int c=0;c<16;c++) acc2[c]=0ULL;

  for (int f=0; f<512; f+=4){
    u64 s2a=0ULL, s2b=0ULL;
    #pragma unroll
    for (int c=0;c<16;c++){
      ulonglong2 kk = *(const ulonglong2*)&Ks[c*ATTN_ROW + f];
      fma2(s2a, q2[c], kk.x);
      fma2(s2b, q2[c], kk.y);
    }
    float2 sa=unpack2(s2a), sb=unpack2(s2b);
    float bm = fmaxf(fmaxf(sa.x,sa.y), fmaxf(sb.x,sb.y));
    if (bm > mmax){
      float sc = __expf(mmax - bm);
      u64 sc2 = pack2(sc, sc);
      mul2(Z2, sc2);
      #pragma unroll
      for (int c=0;c<16;c++) mul2(acc2[c], sc2);
      mmax = bm;
    }
    float w0=__expf(sa.x-mmax), w1=__expf(sa.y-mmax);
    float w2e=__expf(sb.x-mmax), w3e=__expf(sb.y-mmax);
    u64 wa=pack2(w0,w1), wb=pack2(w2e,w3e);
    add2(Z2, wa); add2(Z2, wb);
    #pragma unroll
    for (int c=0;c<16;c++){
      ulonglong2 vv = *(const ulonglong2*)&Vs[c*ATTN_ROW + f];
      fma2(acc2[c], wa, vv.x);
      fma2(acc2[c], wb, vv.y);
    }
  }

  float2 zz = unpack2(Z2);
  float rz = 1.f/(zz.x + zz.y);
  float at[16];
  #pragma unroll
  for (int c=0;c<16;c++){ float2 a=unpack2(acc2[c]); at[c]=(a.x+a.y)*rz; }

  #pragma unroll
  for (int o=0;o<3;o++){
    float sA=0.f;
    #pragma unroll
    for (int c=0;c<16;c++) sA += W3[o*16+c]*at[c];
    g_A3[((size_t)b*3+o)*EE + e] = sA;
  }
}

// ===========================================================================
// Stage C: out = A3·Wo^T + x_p + w3s·bo.  grid (nt=256, mt=2).  CTA 128x64.
// ===========================================================================
__global__ __launch_bounds__(256, 2) void gemm_c_mma(
  const float* __restrict__ x, const float* __restrict__ Wo,
  const float* __restrict__ bo, const float* __restrict__ W3,
  float* __restrict__ out)
{
  extern __shared__ char dynsmem[];
  u32 raw = smem_u32(dynsmem);
  u32 sb = (raw + 1023u) & ~1023u;
  char* sbp = dynsmem + (sb - raw);

  int nt  = blockIdx.x;
  int mtg = blockIdx.y;
  int t   = threadIdx.x;
  int mbase = mtg ? 64 : 0;

  int arow  = t >> 1;
  int khalf = (t & 1) * 16;
  int brow  = t >> 2;
  int bk8   = (t & 3) * 8;

  LoadCtx L;
  L.aptr = g_A3 + ((size_t)(mbase + arow))*EE + khalf;
  L.bptr = Wo   + ((size_t)(nt*64 + brow))*EE + bk8;
  #pragma unroll
  for (int i=0;i<4;i++) L.soA[i] = swa((u32)arow, (u32)(khalf + i*4));
  #pragma unroll
  for (int i=0;i<2;i++) L.soB[i] = swa((u32)brow, (u32)(bk8 + i*4));

  int w = t >> 5, lane = t & 31;
  int wm = w >> 1, wn = w & 1;

  float acc[2][4][4];
  #pragma unroll
  for (int i=0;i<2;i++)
    #pragma unroll
    for (int j=0;j<4;j++)
      #pragma unroll
      for (int q=0;q<4;q++) acc[i][j][q] = 0.f;

  gemm_mainloop(L, sbp, sb, 0, 16, wm, wn, lane, acc);   // K=512 = 16 chunks

  float w3s[3] = {0.f, 0.f, 0.f};
  #pragma unroll
  for (int c=0;c<16;c++){ w3s[0]+=W3[c]; w3s[1]+=W3[16+c]; w3s[2]+=W3[32+c]; }

  int rl = lane >> 2, cl = 2*(lane & 3);
  #pragma unroll
  for (int mt=0; mt<2; mt++){
    #pragma unroll
    for (int half=0; half<2; half++){
      int m = mbase + wm*32 + mt*16 + rl + half*8;
      int b = m/3, o = m - b*3;
      float ws = w3s[o];
      #pragma unroll
      for (int n8=0; n8<4; n8++){
        int tc = nt*64 + wn*32 + n8*8 + cl;
        float2 xv = *(const float2*)(x + ((size_t)(b*7 + o))*TT + tc);
        float2 bv = *(const float2*)(bo + tc);
        float c0 = acc[mt][n8][half*2+0] + xv.x + ws*bv.x;
        float c1 = acc[mt][n8][half*2+1] + xv.y + ws*bv.y;
        *(float2*)&out[(size_t)m*TT + tc] = make_float2(c0, c1);
      }
    }
  }
}

// ===========================================================================
extern "C" void kernel_launch(void* const* d_in, const int* in_sizes, int n_in,
                              void* d_out, int out_size)
{
  const float* x  = (const float*)d_in[0];
  const float* W1 = (const float*)d_in[1];
  const float* W2 = (const float*)d_in[2];
  const float* Wq = (const float*)d_in[3];
  const float* bq = (const float*)d_in[4];
  const float* Wk = (const float*)d_in[5];
  const float* bk = (const float*)d_in[6];
  const float* Wv = (const float*)d_in[7];
  const float* bv = (const float*)d_in[8];
  const float* Wo = (const float*)d_in[9];
  const float* bo = (const float*)d_in[10];
  const float* W3 = (const float*)d_in[11];
  float* out = (float*)d_out;

  static bool attr_set = false;
  if (!attr_set){
    cudaFuncSetAttribute(gemm_a_mma, cudaFuncAttributeMaxDynamicSharedMemorySize, DYN_SMEM);
    cudaFuncSetAttribute(gemm_c_mma, cudaFuncAttributeMaxDynamicSharedMemorySize, DYN_SMEM);
    cudaFuncSetAttribute(attn_kernel, cudaFuncAttributeMaxDynamicSharedMemorySize, ATTN_SMEM);
    attr_set = true;
  }

  gemm_a_mma <<< dim3(8, 6, SPLITS), 256, DYN_SMEM >>> (x, Wq, Wk, Wv);
  reduce_kernel <<< dim3((SLICE_SZ + 255)/256), 256 >>> ();
  attn_kernel <<< dim3(2, NB), 256, ATTN_SMEM >>> (W1, W2, bq, bk, bv, W3);
  gemm_c_mma <<< dim3(256, 2), 256, DYN_SMEM >>> (x, Wo, bo, W3, out);
}

// round 16
// speedup vs baseline: 1.0441x; 1.0441x over previous
#include <cuda_runtime.h>
#include <cstdint>

#define TT 16384
#define EE 512
#define NB 64
#define SPLITS 6

#define SZ_PQ (192*512)
#define SZ_CK (256*512)
#define OFF_PQ 0
#define OFF_CK (SZ_PQ)
#define OFF_CV (SZ_PQ + SZ_CK)
#define SLICE_SZ (SZ_PQ + 2*SZ_CK)   // 360448

__device__ float g_part[SPLITS * SLICE_SZ];
__device__ float g_acc[SLICE_SZ];
__device__ float g_A3[192*512];

typedef unsigned long long u64;
typedef unsigned int u32;

// ===================== packed fp32 helpers ===================
__device__ __forceinline__ u64 pack2(float lo, float hi){
  u64 r; asm("mov.b64 %0, {%1,%2};" : "=l"(r) : "f"(lo), "f"(hi)); return r;
}
__device__ __forceinline__ float2 unpack2(u64 v){
  float2 r; asm("mov.b64 {%0,%1}, %2;" : "=f"(r.x), "=f"(r.y) : "l"(v)); return r;
}
__device__ __forceinline__ void fma2(u64 &d, u64 a, u64 b){
  asm("fma.rn.f32x2 %0, %1, %2, %0;" : "+l"(d) : "l"(a), "l"(b));
}
__device__ __forceinline__ void add2(u64 &d, u64 a){
  asm("add.rn.f32x2 %0, %0, %1;" : "+l"(d) : "l"(a));
}
__device__ __forceinline__ void mul2(u64 &d, u64 a){
  asm("mul.rn.f32x2 %0, %0, %1;" : "+l"(d) : "l"(a));
}

// ===================== mma.sync building blocks ============================
__device__ __forceinline__ u32 smem_u32(const void* p){
  u32 a; asm("{ .reg .u64 t; cvta.to.shared.u64 t, %1; cvt.u32.u64 %0, t; }" : "=r"(a) : "l"(p));
  return a;
}
__device__ __forceinline__ void ldsm4(u32 addr, u32* r){
  asm volatile("ldmatrix.sync.aligned.m8n8.x4.shared.b16 {%0,%1,%2,%3}, [%4];"
    : "=r"(r[0]),"=r"(r[1]),"=r"(r[2]),"=r"(r[3]) : "r"(addr));
}
__device__ __forceinline__ void mma16816(float* c, const u32* a, u32 b0, u32 b1){
  asm volatile("mma.sync.aligned.m16n8k16.row.col.f32.bf16.bf16.f32 "
    "{%0,%1,%2,%3}, {%4,%5,%6,%7}, {%8,%9}, {%0,%1,%2,%3};"
    : "+f"(c[0]),"+f"(c[1]),"+f"(c[2]),"+f"(c[3])
    : "r"(a[0]),"r"(a[1]),"r"(a[2]),"r"(a[3]), "r"(b0),"r"(b1));
}

// fp32x4 -> bf16 hi/lo pairs
__device__ __forceinline__ void cvt_hilo(float4 v, uint2& hi, uint2& lo){
  u32 h01,h23,l01,l23;
  asm("cvt.rn.bf16x2.f32 %0, %1, %2;" : "=r"(h01) : "f"(v.y), "f"(v.x));
  asm("cvt.rn.bf16x2.f32 %0, %1, %2;" : "=r"(h23) : "f"(v.w), "f"(v.z));
  float hx=__uint_as_float(h01<<16), hy=__uint_as_float(h01&0xFFFF0000u);
  float hz=__uint_as_float(h23<<16), hw=__uint_as_float(h23&0xFFFF0000u);
  asm("cvt.rn.bf16x2.f32 %0, %1, %2;" : "=r"(l01) : "f"(v.y-hy), "f"(v.x-hx));
  asm("cvt.rn.bf16x2.f32 %0, %1, %2;" : "=r"(l23) : "f"(v.w-hw), "f"(v.z-hz));
  hi = make_uint2(h01,h23); lo = make_uint2(l01,l23);
}

// Tile geometry: CTA 64(M) x 128(N) x 32(K); bf16 rows of 64B, XOR swizzle.
#define A_TILE_B 4096      // 64 rows x 64B
#define B_TILE_B 8192      // 128 rows x 64B
#define BUF_BYTES (2*A_TILE_B + 2*B_TILE_B)   // 24576: Ahi|Alo|Bhi|Blo
#define DYN_SMEM  (2*BUF_BYTES + 1024)

// attn smem: Ks[16][520] + Vs[16][520] fp32
#define ATTN_ROW   520
#define ATTN_SMEM  (2*16*ATTN_ROW*4)

__device__ __forceinline__ u32 cka(u32 row, u32 kc8){
  return (row*64u + kc8*16u) ^ ((row & 7u) << 4);
}
__device__ __forceinline__ u32 swa(u32 row, u32 k){
  return ((row*64u + ((k>>3)<<4)) ^ ((row & 7u) << 4)) + (k & 4u)*2u;
}

// per-warp compute of one kc=32 chunk; warp tile 32(m)x32(n), 3-term bf16
// warps: wm in 0..1 (m), wn in 0..3 (n)
__device__ __forceinline__ void chunk_compute(
    u32 sAhi, u32 sAlo, u32 sBhi, u32 sBlo,
    int wm, int wn, int lane, float acc[2][4][4])
{
  u32 lrow = lane & 15, lkh = (u32)lane >> 4;
  #pragma unroll
  for (int s=0; s<2; s++){
    u32 kc8 = 2u*s + lkh;
    u32 bh[2][4], bl[2][4];
    #pragma unroll
    for (int nt2=0; nt2<2; nt2++){
      u32 off = cka((u32)(wn*32 + nt2*16) + lrow, kc8);
      ldsm4(sBhi + off, bh[nt2]);
      ldsm4(sBlo + off, bl[nt2]);
    }
    #pragma unroll
    for (int mt=0; mt<2; mt++){
      u32 ah[4], al[4];
      u32 off = cka((u32)(wm*32 + mt*16) + lrow, kc8);
      ldsm4(sAhi + off, ah);
      ldsm4(sAlo + off, al);
      #pragma unroll
      for (int n8=0; n8<4; n8++){
        int g = n8 >> 1, o = n8 & 1;
        u32 b0h = bh[g][o], b1h = bh[g][o+2];
        u32 b0l = bl[g][o], b1l = bl[g][o+2];
        mma16816(acc[mt][n8], ah, b0h, b1h);
        mma16816(acc[mt][n8], ah, b0l, b1l);
        mma16816(acc[mt][n8], al, b0h, b1h);
      }
    }
  }
}

// loader: 256 threads fill 64x32 A tile (2 float4/thread) + 128x32 B tile
// (4 float4/thread).
// A: thread t -> row t>>2, k = (t&3)*8 + {0,4}
// B: thread t -> row t>>1, k = (t&1)*16 + {0,4,8,12}
struct LoadCtx {
  const float* aptr;   // A row base + ak8
  const float* bptr;   // B row base + khalf
  u32 soA[2];
  u32 soB[4];
};

__device__ __forceinline__ void fill_buf(const LoadCtx& L, char* base, int kb){
  #pragma unroll
  for (int i=0;i<2;i++){
    float4 v = *(const float4*)(L.aptr + kb + i*4);
    uint2 hi, lo;
    cvt_hilo(v, hi, lo);
    *(uint2*)(base + L.soA[i]) = hi;
    *(uint2*)(base + A_TILE_B + L.soA[i]) = lo;
  }
  #pragma unroll
  for (int i=0;i<4;i++){
    float4 v = *(const float4*)(L.bptr + kb + i*4);
    uint2 hi, lo;
    cvt_hilo(v, hi, lo);
    *(uint2*)(base + 2*A_TILE_B + L.soB[i]) = hi;
    *(uint2*)(base + 2*A_TILE_B + B_TILE_B + L.soB[i]) = lo;
  }
}

__device__ __forceinline__ void fill_buf_pref(
    const LoadCtx& L, char* base, const float4* ga, const float4* gb){
  #pragma unroll
  for (int i=0;i<2;i++){
    uint2 hi, lo;
    cvt_hilo(ga[i], hi, lo);
    *(uint2*)(base + L.soA[i]) = hi;
    *(uint2*)(base + A_TILE_B + L.soA[i]) = lo;
  }
  #pragma unroll
  for (int i=0;i<4;i++){
    uint2 hi, lo;
    cvt_hilo(gb[i], hi, lo);
    *(uint2*)(base + 2*A_TILE_B + L.soB[i]) = hi;
    *(uint2*)(base + 2*A_TILE_B + B_TILE_B + L.soB[i]) = lo;
  }
}

// 32-k chunks, double-buffered, single-chunk register prefetch
__device__ __forceinline__ void gemm_mainloop(
    const LoadCtx& L, char* sbp, u32 sb, int cs, int nch,
    int wm, int wn, int lane, float acc[2][4][4])
{
  fill_buf(L, sbp, cs*32);
  __syncthreads();

  for (int c = 0; c < nch; c++){
    int buf = c & 1;
    float4 ga[2], gb[4];
    if (c + 1 < nch){
      int kb = (cs + c + 1)*32;
      #pragma unroll
      for (int i=0;i<2;i++) ga[i] = *(const float4*)(L.aptr + kb + i*4);
      #pragma unroll
      for (int i=0;i<4;i++) gb[i] = *(const float4*)(L.bptr + kb + i*4);
    }
    u32 bufb = sb + (u32)buf*BUF_BYTES;
    chunk_compute(bufb, bufb+A_TILE_B, bufb+2*A_TILE_B, bufb+2*A_TILE_B+B_TILE_B,
                  wm, wn, lane, acc);
    if (c + 1 < nch){
      fill_buf_pref(L, sbp + (buf^1)*BUF_BYTES, ga, gb);
    }
    __syncthreads();
  }
}

// ===========================================================================
// Stage A: partial GEMMs (PQ/CK/CV), split-K.  grid (nt=4, mrow=11, s=6)
// m-tiles of 64 rows: Q rows 0..191 (3), K rows (4), V rows (4). No overlap.
// ===========================================================================
__global__ __launch_bounds__(256, 2) void gemm_a_mma(
    const float* __restrict__ x, const float* __restrict__ Wq,
    const float* __restrict__ Wk, const float* __restrict__ Wv)
{
  extern __shared__ char dynsmem[];
  u32 raw = smem_u32(dynsmem);
  u32 sb = (raw + 1023u) & ~1023u;
  char* sbp = dynsmem + (sb - raw);

  int nt   = blockIdx.x;
  int mrow = blockIdx.y;   // 0..10
  int s    = blockIdx.z;
  int t    = threadIdx.x;

  int mat, mbase;
  if (mrow < 3)      { mat = 0; mbase = mrow*64; }
  else if (mrow < 7) { mat = 1; mbase = (mrow-3)*64; }
  else               { mat = 2; mbase = (mrow-7)*64; }
  const float* __restrict__ W = (mat==0) ? Wq : (mat==1) ? Wk : Wv;
  int obase = (mat==0) ? OFF_PQ : (mat==1) ? OFF_CK : OFF_CV;

  // 512 chunks of 32 over 6 splits (2 x 86 + 4 x 85 = 512)
  int cs  = s*85 + min(s, 2);
  int nch = 85 + (s < 2 ? 1 : 0);

  int arow = t >> 2;
  int ak8  = (t & 3) * 8;
  int brow = t >> 1;
  int bkh  = (t & 1) * 16;

  int m = mbase + arow;
  int b, ch;
  if (mat == 0){ b = m/3; ch = m - b*3; }
  else         { b = m/4; ch = 3 + (m - b*4); }

  LoadCtx L;
  L.aptr = x + ((size_t)(b*7 + ch))*TT + ak8;
  L.bptr = W + ((size_t)(nt*128 + brow))*TT + bkh;
  #pragma unroll
  for (int i=0;i<2;i++) L.soA[i] = swa((u32)arow, (u32)(ak8 + i*4));
  #pragma unroll
  for (int i=0;i<4;i++) L.soB[i] = swa((u32)brow, (u32)(bkh + i*4));

  int w = t >> 5, lane = t & 31;
  int wm = w >> 2, wn = w & 3;

  float acc[2][4][4];
  #pragma unroll
  for (int i=0;i<2;i++)
    #pragma unroll
    for (int j=0;j<4;j++)
      #pragma unroll
      for (int q=0;q<4;q++) acc[i][j][q] = 0.f;

  gemm_mainloop(L, sbp, sb, cs, nch, wm, wn, lane, acc);

  float* dst = g_part + (size_t)s*SLICE_SZ + obase;
  int rl = lane >> 2, cl = 2*(lane & 3);
  #pragma unroll
  for (int mt=0; mt<2; mt++){
    int r0 = mbase + wm*32 + mt*16 + rl;
    #pragma unroll
    for (int n8=0; n8<4; n8++){
      int col = nt*128 + wn*32 + n8*8 + cl;
      *(float2*)&dst[(size_t)r0*EE + col]     = make_float2(acc[mt][n8][0], acc[mt][n8][1]);
      *(float2*)&dst[(size_t)(r0+8)*EE + col] = make_float2(acc[mt][n8][2], acc[mt][n8][3]);
    }
  }
}

// ===========================================================================
// Split-K reduction (deterministic)
// ===========================================================================
__global__ __launch_bounds__(256) void reduce_kernel()
{
  int i = blockIdx.x*256 + threadIdx.x;
  if (i >= SLICE_SZ) return;
  float s = 0.f;
  #pragma unroll
  for (int sl=0; sl<SPLITS; sl++) s += g_part[(size_t)sl*SLICE_SZ + i];
  g_acc[i] = s;
}

// ===========================================================================
// Attention (R14 best-measured form): K/V built per block, online softmax.
// grid (4 e-chunks, NB batches), 128 threads; dynamic smem 65 KB.
// ===========================================================================
__global__ __launch_bounds__(128) void attn_kernel(
  const float* __restrict__ W1, const float* __restrict__ W2,
  const float* __restrict__ bq, const float* __restrict__ bk,
  const float* __restrict__ bv, const float* __restrict__ W3)
{
  extern __shared__ float sKV[];
  float* Ks = sKV;
  float* Vs = sKV + 16*ATTN_ROW;

  int b = blockIdx.y;
  int t = threadIdx.x;
  int e = blockIdx.x*128 + t;

  const float* __restrict__ PQb = g_acc + OFF_PQ + (size_t)b*3*EE;
  const float* __restrict__ CKb = g_acc + OFF_CK + (size_t)b*4*EE;
  const float* __restrict__ CVb = g_acc + OFF_CV + (size_t)b*4*EE;

  #pragma unroll
  for (int r=0; r<4; r++){
    int f = r*128 + t;
    float k0 = CKb[f], k1 = CKb[EE+f], k2 = CKb[2*EE+f], k3 = CKb[3*EE+f];
    float v0 = CVb[f], v1 = CVb[EE+f], v2 = CVb[2*EE+f], v3 = CVb[3*EE+f];
    float bkf = bk[f], bvf = bv[f];
    #pragma unroll
    for (int c=0;c<16;c++){
      const float* w2 = W2 + c*4;
      Ks[c*ATTN_ROW + f] = w2[0]*k0 + w2[1]*k1 + w2[2]*k2 + w2[3]*k3 + bkf;
      Vs[c*ATTN_ROW + f] = w2[0]*v0 + w2[1]*v1 + w2[2]*v2 + w2[3]*v3 + bvf;
    }
  }

  float p0 = PQb[e], p1 = PQb[EE+e], p2 = PQb[2*EE+e];
  float bqe = bq[e];
  u64 q2[16];
  #pragma unroll
  for (int c=0;c<16;c++){
    float qc = 0.25f*(W1[c*3]*p0 + W1[c*3+1]*p1 + W1[c*3+2]*p2 + bqe);
    q2[c] = pack2(qc, qc);
  }
  __syncthreads();

  float mmax = -1e30f;
  u64 Z2 = 0ULL;
  u64 acc2[16];
  #pragma unroll
  for (int c=0;c<16;c++) acc2[c]=0ULL;

  for (int f=0; f<512; f+=4){
    u64 s2a=0ULL, s2b=0ULL;
    #pragma unroll
    for (int c=0;c<16;c++){
      ulonglong2 kk = *(const ulonglong2*)&Ks[c*ATTN_ROW + f];
      fma2(s2a, q2[c], kk.x);
      fma2(s2b, q2[c], kk.y);
    }
    float2 sa=unpack2(s2a), sb=unpack2(s2b);
    float bm = fmaxf(fmaxf(sa.x,sa.y), fmaxf(sb.x,sb.y));
    if (bm > mmax){
      float sc = __expf(mmax - bm);
      u64 sc2 = pack2(sc, sc);
      mul2(Z2, sc2);
      #pragma unroll
      for (int c=0;c<16;c++) mul2(acc2[c], sc2);
      mmax = bm;
    }
    float w0=__expf(sa.x-mmax), w1=__expf(sa.y-mmax);
    float w2e=__expf(sb.x-mmax), w3e=__expf(sb.y-mmax);
    u64 wa=pack2(w0,w1), wb=pack2(w2e,w3e);
    add2(Z2, wa); add2(Z2, wb);
    #pragma unroll
    for (int c=0;c<16;c++){
      ulonglong2 vv = *(const ulonglong2*)&Vs[c*ATTN_ROW + f];
      fma2(acc2[c], wa, vv.x);
      fma2(acc2[c], wb, vv.y);
    }
  }

  float2 zz = unpack2(Z2);
  float rz = 1.f/(zz.x + zz.y);
  float at[16];
  #pragma unroll
  for (int c=0;c<16;c++){ float2 a=unpack2(acc2[c]); at[c]=(a.x+a.y)*rz; }

  #pragma unroll
  for (int o=0;o<3;o++){
    float sA=0.f;
    #pragma unroll
    for (int c=0;c<16;c++) sA += W3[o*16+c]*at[c];
    g_A3[((size_t)b*3+o)*EE + e] = sA;
  }
}

// ===========================================================================
// Stage C: out = A3·Wo^T + x_p + w3s·bo.  grid (nt=128, mrow=3).  CTA 64x128.
// ===========================================================================
__global__ __launch_bounds__(256, 2) void gemm_c_mma(
  const float* __restrict__ x, const float* __restrict__ Wo,
  const float* __restrict__ bo, const float* __restrict__ W3,
  float* __restrict__ out)
{
  extern __shared__ char dynsmem[];
  u32 raw = smem_u32(dynsmem);
  u32 sb = (raw + 1023u) & ~1023u;
  char* sbp = dynsmem + (sb - raw);

  int nt   = blockIdx.x;
  int mrow = blockIdx.y;    // 0..2 -> rows mrow*64 .. +63
  int t    = threadIdx.x;
  int mbase = mrow*64;

  int arow = t >> 2;
  int ak8  = (t & 3) * 8;
  int brow = t >> 1;
  int bkh  = (t & 1) * 16;

  LoadCtx L;
  L.aptr = g_A3 + ((size_t)(mbase + arow))*EE + ak8;
  L.bptr = Wo   + ((size_t)(nt*128 + brow))*EE + bkh;
  #pragma unroll
  for (int i=0;i<2;i++) L.soA[i] = swa((u32)arow, (u32)(ak8 + i*4));
  #pragma unroll
  for (int i=0;i<4;i++) L.soB[i] = swa((u32)brow, (u32)(bkh + i*4));

  int w = t >> 5, lane = t & 31;
  int wm = w >> 2, wn = w & 3;

  float acc[2][4][4];
  #pragma unroll
  for (int i=0;i<2;i++)
    #pragma unroll
    for (int j=0;j<4;j++)
      #pragma unroll
      for (int q=0;q<4;q++) acc[i][j][q] = 0.f;

  gemm_mainloop(L, sbp, sb, 0, 16, wm, wn, lane, acc);   // K=512 = 16 chunks

  float w3s[3] = {0.f, 0.f, 0.f};
  #pragma unroll
  for (int c=0;c<16;c++){ w3s[0]+=W3[c]; w3s[1]+=W3[16+c]; w3s[2]+=W3[32+c]; }

  int rl = lane >> 2, cl = 2*(lane & 3);
  #pragma unroll
  for (int mt=0; mt<2; mt++){
    #pragma unroll
    for (int half=0; half<2; half++){
      int m = mbase + wm*32 + mt*16 + rl + half*8;
      int b = m/3, o = m - b*3;
      float ws = w3s[o];
      #pragma unroll
      for (int n8=0; n8<4; n8++){
        int tc = nt*128 + wn*32 + n8*8 + cl;
        float2 xv = *(const float2*)(x + ((size_t)(b*7 + o))*TT + tc);
        float2 bv = *(const float2*)(bo + tc);
        float c0 = acc[mt][n8][half*2+0] + xv.x + ws*bv.x;
        float c1 = acc[mt][n8][half*2+1] + xv.y + ws*bv.y;
        *(float2*)&out[(size_t)m*TT + tc] = make_float2(c0, c1);
      }
    }
  }
}

// ===========================================================================
extern "C" void kernel_launch(void* const* d_in, const int* in_sizes, int n_in,
                              void* d_out, int out_size)
{
  const float* x  = (const float*)d_in[0];
  const float* W1 = (const float*)d_in[1];
  const float* W2 = (const float*)d_in[2];
  const float* Wq = (const float*)d_in[3];
  const float* bq = (const float*)d_in[4];
  const float* Wk = (const float*)d_in[5];
  const float* bk = (const float*)d_in[6];
  const float* Wv = (const float*)d_in[7];
  const float* bv = (const float*)d_in[8];
  const float* Wo = (const float*)d_in[9];
  const float* bo = (const float*)d_in[10];
  const float* W3 = (const float*)d_in[11];
  float* out = (float*)d_out;

  static bool attr_set = false;
  if (!attr_set){
    cudaFuncSetAttribute(gemm_a_mma, cudaFuncAttributeMaxDynamicSharedMemorySize, DYN_SMEM);
    cudaFuncSetAttribute(gemm_c_mma, cudaFuncAttributeMaxDynamicSharedMemorySize, DYN_SMEM);
    cudaFuncSetAttribute(attn_kernel, cudaFuncAttributeMaxDynamicSharedMemorySize, ATTN_SMEM);
    attr_set = true;
  }

  gemm_a_mma <<< dim3(4, 11, SPLITS), 256, DYN_SMEM >>> (x, Wq, Wk, Wv);
  reduce_kernel <<< dim3((SLICE_SZ + 255)/256), 256 >>> ();
  attn_kernel <<< dim3(4, NB), 128, ATTN_SMEM >>> (W1, W2, bq, bk, bv, W3);
  gemm_c_mma <<< dim3(128, 3), 256, DYN_SMEM >>> (x, Wo, bo, W3, out);
}